// round 15
// baseline (speedup 1.0000x reference)
#include <cuda_runtime.h>
#include <cuda_fp16.h>
#include <math.h>
#include <stdint.h>

#define S_LEN   2048
#define B_SZ    32
#define D_SZ    512
#define H_SZ    512
#define N3      1536            // 3*H
#define M_SZ    (S_LEN * B_SZ)  // 65536
#define K_SZ    512
#define CHUNK   32
#define NCHUNK  (S_LEN / CHUNK) // 64
#define NCH     (B_SZ * H_SZ)   // 16384
#define C_SZ    10

// ---------------- GEMM tiling ----------------
#define BM 128
#define BN 128
#define BK 32
#define KT_ITERS (K_SZ / BK)    // 16
#define PAIRS (KT_ITERS / 2)    // 8
#define STAGES 6                // 3 pair-slots
#define MTILES (M_SZ / BM)      // 512
#define NTILES (N3 / BN)        // 12

// smem pitches (bytes), padded for conflict-free ldmatrix
#define A_PITCH 80              // 32 fp16 = 64B + 16B pad
#define B_PITCH 272             // 128 fp16 = 256B + 16B pad
#define ST_A    0
#define ST_B    (BM * A_PITCH)                 // 10240
#define ST_BYTES (BM * A_PITCH + BK * B_PITCH) // 18944
#define DYN_SMEM (STAGES * ST_BYTES)           // 113664 -> 2 CTAs/SM
// epilogue staging reuses pipeline smem: 128 rows x 272 B = 34816 B < DYN_SMEM
#define EPI_PITCH 272

// ---------------- scratch (device globals: allocation-free rule) ----------------
__device__ __half  g_U  [(size_t)M_SZ * N3];    // 192 MB (fp16 U)
__device__ __half  g_AhA[(size_t)M_SZ * K_SZ];  // 64 MB  (fp16 h, buffer A)
__device__ __half  g_AhB[(size_t)M_SZ * K_SZ];  // 64 MB  (fp16 h, buffer B)
__device__ __half  g_Bh [2 * K_SZ * N3];        // 3 MB   (fp16 W)
__device__ float   g_Ac[NCHUNK * NCH];
__device__ float   g_Bc[NCHUNK * NCH];
__device__ float   g_ci[NCHUNK * NCH];
__device__ float   g_pm[NCHUNK * NCH];          // 4 MB (chunk-level max)
__device__ float   g_pool[NCH];

// ---------------- PTX helpers ----------------
__device__ __forceinline__ uint32_t smem_u32(const void* p) {
    uint32_t a;
    asm("{ .reg .u64 t; cvta.to.shared.u64 t, %1; cvt.u32.u64 %0, t; }" : "=r"(a) : "l"(p));
    return a;
}

__device__ __forceinline__ void cp16(uint32_t dst, const void* src) {
    asm volatile("cp.async.cg.shared.global [%0], [%1], 16;" :: "r"(dst), "l"(src));
}
#define CP_COMMIT() asm volatile("cp.async.commit_group;" ::: "memory")
#define CP_WAIT(n)  asm volatile("cp.async.wait_group %0;" :: "n"(n) : "memory")

__device__ __forceinline__ void ldsm_x4(uint32_t& r0, uint32_t& r1, uint32_t& r2, uint32_t& r3,
                                        uint32_t addr) {
    asm volatile("ldmatrix.sync.aligned.m8n8.x4.shared.b16 {%0,%1,%2,%3}, [%4];"
                 : "=r"(r0), "=r"(r1), "=r"(r2), "=r"(r3) : "r"(addr));
}
__device__ __forceinline__ void ldsm_x4_t(uint32_t& r0, uint32_t& r1, uint32_t& r2, uint32_t& r3,
                                          uint32_t addr) {
    asm volatile("ldmatrix.sync.aligned.m8n8.x4.trans.shared.b16 {%0,%1,%2,%3}, [%4];"
                 : "=r"(r0), "=r"(r1), "=r"(r2), "=r"(r3) : "r"(addr));
}

__device__ __forceinline__ void mma_f16(float& c0, float& c1, float& c2, float& c3,
                                        uint32_t a0, uint32_t a1, uint32_t a2, uint32_t a3,
                                        uint32_t b0, uint32_t b1) {
    asm volatile(
        "mma.sync.aligned.m16n8k16.row.col.f32.f16.f16.f32 "
        "{%0,%1,%2,%3}, {%4,%5,%6,%7}, {%8,%9}, {%0,%1,%2,%3};"
        : "+f"(c0), "+f"(c1), "+f"(c2), "+f"(c3)
        : "r"(a0), "r"(a1), "r"(a2), "r"(a3), "r"(b0), "r"(b1));
}

__device__ __forceinline__ float sigm(float x) { return 1.0f / (1.0f + expf(-x)); }

// ---------------- fp16 pack/unpack helpers ----------------
__device__ __forceinline__ uint2 pack_h4(float4 a) {
    __half2 p0 = __floats2half2_rn(a.x, a.y);
    __half2 p1 = __floats2half2_rn(a.z, a.w);
    uint2 r;
    r.x = *reinterpret_cast<uint32_t*>(&p0);
    r.y = *reinterpret_cast<uint32_t*>(&p1);
    return r;
}
__device__ __forceinline__ void unp8(uint4 v, float* o) {
    float2 a = __half22float2(*reinterpret_cast<__half2*>(&v.x));
    float2 b = __half22float2(*reinterpret_cast<__half2*>(&v.y));
    float2 c = __half22float2(*reinterpret_cast<__half2*>(&v.z));
    float2 d = __half22float2(*reinterpret_cast<__half2*>(&v.w));
    o[0] = a.x; o[1] = a.y; o[2] = b.x; o[3] = b.y;
    o[4] = c.x; o[5] = c.y; o[6] = d.x; o[7] = d.y;
}

// ---------------- embedding gather -> fp16 h ----------------
__global__ void gather_kernel(const int* __restrict__ x,
                              const float* __restrict__ embed,
                              __half* __restrict__ ah) {
    size_t idx = (size_t)blockIdx.x * blockDim.x + threadIdx.x;
    int m = (int)(idx >> 7);
    int j = (int)(idx & 127);
    int row = x[m];
    float4 a = reinterpret_cast<const float4*>(embed)[(size_t)row * 128 + j];
    reinterpret_cast<uint2*>(ah)[idx] = pack_h4(a);
}

// ---------------- weight conversion: fp32 -> fp16 ----------------
__global__ void convert_kernel(const float* __restrict__ src,
                               __half* __restrict__ dst) {
    size_t idx = (size_t)blockIdx.x * blockDim.x + threadIdx.x;
    float4 a = reinterpret_cast<const float4*>(src)[idx];
    reinterpret_cast<uint2*>(dst)[idx] = pack_h4(a);
}

// ---------------- fp16 HMMA GEMM: 128x128x512, paired K pipeline, staged epilogue ----------------
__global__ __launch_bounds__(256, 2) void gemm_mma_kernel(
    const __half* __restrict__ Ah,
    const __half* __restrict__ Bh,
    const float* __restrict__ bias,   // 1024 (f then r)
    __half* __restrict__ U)
{
    extern __shared__ __align__(1024) char smem[];
    __shared__ float s_bias[BN];

    const int tid = threadIdx.x;
    const int lane = tid & 31;
    const int wid = tid >> 5;
    const int wm = wid >> 2;
    const int wn = wid & 3;
    const int ntile = blockIdx.x;
    const int mtile = blockIdx.y;
    const int n0 = ntile * BN;
    const int m0 = mtile * BM;
    const bool gate = (n0 >= 512);

    if (tid < BN) s_bias[tid] = gate ? bias[n0 - 512 + tid] : 0.0f;

    const uint32_t sbase = smem_u32(smem);
    const int lrow = lane & 15;
    const int lcol8 = (lane >> 4) * 8;

    // One stage: A 128 rows x 4 chunks = 512 cp16 ; B 32 rows x 16 chunks = 512 cp16.
    // load_pair loads stages 2p, 2p+1 into pair-slot (2 stages), ONE commit group.
    auto load_pair = [&](int p, int slot) {
#pragma unroll
        for (int sub = 0; sub < 2; sub++) {
            uint32_t sb = sbase + (slot * 2 + sub) * ST_BYTES;
            int kk = (p * 2 + sub) * BK;
#pragma unroll
            for (int c = 0; c < 2; c++) {
                int ci = tid + c * 256;
                int am = ci >> 2, ak = ci & 3;
                cp16(sb + ST_A + am * A_PITCH + ak * 16,
                     Ah + (size_t)(m0 + am) * K_SZ + kk + ak * 8);
                int bk = ci >> 4, bq = ci & 15;
                cp16(sb + ST_B + bk * B_PITCH + bq * 16,
                     Bh + (size_t)(kk + bk) * N3 + n0 + bq * 8);
            }
        }
    };

    float acc[4][4][4];
#pragma unroll
    for (int i = 0; i < 4; i++)
#pragma unroll
        for (int j = 0; j < 4; j++)
#pragma unroll
            for (int q = 0; q < 4; q++) acc[i][j][q] = 0.0f;

    // prologue: pairs 0,1 into slots 0,1
    load_pair(0, 0); CP_COMMIT();
    load_pair(1, 1); CP_COMMIT();

    for (int p = 0; p < PAIRS; p++) {
        const int slot = p % 3;
        CP_WAIT(1);
        __syncthreads();   // pair p readable by all; slot (p+2)%3 = (p-1)%3 drained

        if (p + 2 < PAIRS) load_pair(p + 2, (p + 2) % 3);
        CP_COMMIT();       // unconditional: keeps wait_group counting aligned

#pragma unroll
        for (int sub = 0; sub < 2; sub++) {
            const uint32_t sb = sbase + (slot * 2 + sub) * ST_BYTES;
            const uint32_t sA = sb + ST_A + (wm * 64 + lrow) * A_PITCH;
            const uint32_t sB = sb + ST_B + lrow * B_PITCH + (wn * 32 + lcol8) * 2;

#pragma unroll
            for (int k16 = 0; k16 < 2; k16++) {
                uint32_t bh[2][4];
#pragma unroll
                for (int nj = 0; nj < 2; nj++) {
                    uint32_t bo = k16 * 16 * B_PITCH + nj * 16 * 2;
                    ldsm_x4_t(bh[nj][0], bh[nj][1], bh[nj][2], bh[nj][3], sB + bo);
                }
#pragma unroll
                for (int mi = 0; mi < 4; mi++) {
                    uint32_t ah[4];
                    uint32_t ao = mi * 16 * A_PITCH + (k16 * 16 + lcol8) * 2;
                    ldsm_x4(ah[0], ah[1], ah[2], ah[3], sA + ao);
#pragma unroll
                    for (int n8 = 0; n8 < 4; n8++) {
                        float* c = acc[mi][n8];
                        mma_f16(c[0], c[1], c[2], c[3], ah[0], ah[1], ah[2], ah[3],
                                bh[n8 >> 1][(n8 & 1) * 2], bh[n8 >> 1][(n8 & 1) * 2 + 1]);
                    }
                }
            }
        }
    }

    // ---- epilogue: gate in registers -> smem staging -> coalesced uint4 stores ----
    __syncthreads();   // all pipeline smem reads complete before overwrite
    const int g = lane >> 2;
    const int tig = lane & 3;
#pragma unroll
    for (int mi = 0; mi < 4; mi++) {
        int row_l = wm * 64 + mi * 16 + g;
#pragma unroll
        for (int n8 = 0; n8 < 4; n8++) {
            int coll = wn * 32 + n8 * 8 + tig * 2;
            float v0 = acc[mi][n8][0], v1 = acc[mi][n8][1];
            float v2 = acc[mi][n8][2], v3 = acc[mi][n8][3];
            if (gate) {
                float b0 = s_bias[coll], b1 = s_bias[coll + 1];
                v0 = sigm(v0 + b0); v1 = sigm(v1 + b1);
                v2 = sigm(v2 + b0); v3 = sigm(v3 + b1);
            }
            *reinterpret_cast<__half2*>(smem + row_l * EPI_PITCH + coll * 2) =
                __floats2half2_rn(v0, v1);
            *reinterpret_cast<__half2*>(smem + (row_l + 8) * EPI_PITCH + coll * 2) =
                __floats2half2_rn(v2, v3);
        }
    }
    __syncthreads();
    // 128 rows x 16 uint4 per row = 2048 chunks; 8 per thread; contiguous 256B rows
#pragma unroll
    for (int j = 0; j < 8; j++) {
        int idx = tid + j * 256;
        int row = idx >> 4, q = idx & 15;
        uint4 v = *reinterpret_cast<uint4*>(smem + row * EPI_PITCH + q * 16);
        *reinterpret_cast<uint4*>(&U[(size_t)(m0 + row) * N3 + n0 + q * 8]) = v;
    }
}

// ---------------- scan pass A: per-chunk affine composition (8 channels/thread) ----------------
__global__ void scan_passA(const __half* __restrict__ U,
                           float* __restrict__ Ac, float* __restrict__ Bc) {
    int t = blockIdx.x * blockDim.x + threadIdx.x;   // NCHUNK*NCH/8
    int chv = t & (NCH / 8 - 1);
    int chunk = t >> 11;
    int ch0 = chv * 8;
    int b = ch0 >> 9;
    int h = ch0 & 511;
    const __half* fp = U + ((size_t)(chunk * CHUNK * B_SZ + b)) * N3 + 512 + h;
    float Aa[8], Bb[8];
#pragma unroll
    for (int j = 0; j < 8; j++) { Aa[j] = 1.0f; Bb[j] = 0.0f; }
#pragma unroll 4
    for (int i = 0; i < CHUNK; i++) {
        float f[8], xt[8];
        unp8(*reinterpret_cast<const uint4*>(fp), f);
        unp8(*reinterpret_cast<const uint4*>(fp - 512), xt);
#pragma unroll
        for (int j = 0; j < 8; j++) {
            Bb[j] = f[j] * Bb[j] + (1.0f - f[j]) * xt[j];
            Aa[j] *= f[j];
        }
        fp += (size_t)B_SZ * N3;
    }
    int base = chunk * NCH + ch0;
    *reinterpret_cast<float4*>(&Ac[base])     = make_float4(Aa[0], Aa[1], Aa[2], Aa[3]);
    *reinterpret_cast<float4*>(&Ac[base + 4]) = make_float4(Aa[4], Aa[5], Aa[6], Aa[7]);
    *reinterpret_cast<float4*>(&Bc[base])     = make_float4(Bb[0], Bb[1], Bb[2], Bb[3]);
    *reinterpret_cast<float4*>(&Bc[base + 4]) = make_float4(Bb[4], Bb[5], Bb[6], Bb[7]);
}

// ---------------- scan pass B: prefix over chunks (4 channels/thread) ----------------
__global__ void scan_passB(const float* __restrict__ Ac,
                           const float* __restrict__ Bc,
                           float* __restrict__ ci) {
    int t = blockIdx.x * blockDim.x + threadIdx.x;   // NCH/4
    int ch0 = t * 4;
    float4 c = make_float4(0.f, 0.f, 0.f, 0.f);
#pragma unroll 8
    for (int k = 0; k < NCHUNK; k++) {
        int base = k * NCH + ch0;
        *reinterpret_cast<float4*>(&ci[base]) = c;
        float4 A = *reinterpret_cast<const float4*>(&Ac[base]);
        float4 B = *reinterpret_cast<const float4*>(&Bc[base]);
        c.x = A.x * c.x + B.x;
        c.y = A.y * c.y + B.y;
        c.z = A.z * c.z + B.z;
        c.w = A.w * c.w + B.w;
    }
}

// ---------------- scan pass C: rescan + highway output (8 channels/thread) ----------------
// mode 0: write fp16 h_out ; mode 1: final layer -> per-chunk max only
__global__ void scan_passC(const __half* __restrict__ U,
                           const float* __restrict__ ci,
                           const __half* __restrict__ hin,
                           __half* __restrict__ hout,
                           float* __restrict__ pm,
                           int mode) {
    int t = blockIdx.x * blockDim.x + threadIdx.x;   // NCHUNK*NCH/8
    int chv = t & (NCH / 8 - 1);
    int chunk = t >> 11;
    int ch0 = chv * 8;
    int b = ch0 >> 9;
    int h = ch0 & 511;
    size_t m0 = (size_t)(chunk * CHUNK * B_SZ + b);
    const __half* fp = U + m0 * N3 + 512 + h;
    size_t hoff = m0 * H_SZ + h;
    int cbase = chunk * NCH + ch0;

    float c[8], mx[8];
    *reinterpret_cast<float4*>(&c[0]) = *reinterpret_cast<const float4*>(&ci[cbase]);
    *reinterpret_cast<float4*>(&c[4]) = *reinterpret_cast<const float4*>(&ci[cbase + 4]);
#pragma unroll
    for (int j = 0; j < 8; j++) mx[j] = -INFINITY;

#pragma unroll 2
    for (int i = 0; i < CHUNK; i++) {
        float f[8], xt[8], r[8], hv[8];
        unp8(*reinterpret_cast<const uint4*>(fp), f);
        unp8(*reinterpret_cast<const uint4*>(fp - 512), xt);
        unp8(*reinterpret_cast<const uint4*>(fp + 512), r);
        unp8(*reinterpret_cast<const uint4*>(&hin[hoff]), hv);
        if (mode == 0) {
            __half ob[8];
#pragma unroll
            for (int j = 0; j < 8; j++) {
                c[j] = f[j] * c[j] + (1.0f - f[j]) * xt[j];
                float o = r[j] * tanhf(c[j]) + (1.0f - r[j]) * hv[j];
                ob[j] = __float2half_rn(o);
            }
            *reinterpret_cast<uint4*>(&hout[hoff]) = *reinterpret_cast<uint4*>(ob);
        } else {
#pragma unroll
            for (int j = 0; j < 8; j++) {
                c[j] = f[j] * c[j] + (1.0f - f[j]) * xt[j];
                float o = r[j] * tanhf(c[j]) + (1.0f - r[j]) * hv[j];
                mx[j] = fmaxf(mx[j], o);
            }
        }
        fp += (size_t)B_SZ * N3;
        hoff += (size_t)B_SZ * H_SZ;
    }
    if (mode == 1) {
        *reinterpret_cast<float4*>(&pm[cbase])     = make_float4(mx[0], mx[1], mx[2], mx[3]);
        *reinterpret_cast<float4*>(&pm[cbase + 4]) = make_float4(mx[4], mx[5], mx[6], mx[7]);
    }
}

// ---------------- pool reduce over chunks (4 channels/thread) ----------------
__global__ void pool_reduce(const float* __restrict__ pm, float* __restrict__ pool) {
    int t = blockIdx.x * blockDim.x + threadIdx.x;   // NCH/4
    int ch0 = t * 4;
    float4 mx = make_float4(-INFINITY, -INFINITY, -INFINITY, -INFINITY);
#pragma unroll 8
    for (int s = 0; s < NCHUNK; s++) {
        float4 v = *reinterpret_cast<const float4*>(&pm[s * NCH + ch0]);
        mx.x = fmaxf(mx.x, v.x); mx.y = fmaxf(mx.y, v.y);
        mx.z = fmaxf(mx.z, v.z); mx.w = fmaxf(mx.w, v.w);
    }
    pool[ch0]     = tanhf(tanhf(mx.x));
    pool[ch0 + 1] = tanhf(tanhf(mx.y));
    pool[ch0 + 2] = tanhf(tanhf(mx.z));
    pool[ch0 + 3] = tanhf(tanhf(mx.w));
}

// ---------------- tiny classifier ----------------
__global__ void classifier_kernel(const float* __restrict__ pool,
                                  const float* __restrict__ Wc,
                                  const float* __restrict__ bc,
                                  float* __restrict__ out) {
    int tid = threadIdx.x;
    int b = tid / C_SZ;
    int c = tid % C_SZ;
    float s = bc[c];
    const float* p = pool + b * H_SZ;
#pragma unroll 8
    for (int h = 0; h < H_SZ; h++) s += p[h] * Wc[h * C_SZ + c];
    out[b * C_SZ + c] = s;
}

// ---------------- launch ----------------
extern "C" void kernel_launch(void* const* d_in, const int* in_sizes, int n_in,
                              void* d_out, int out_size) {
    const int*   x     = (const int*)d_in[0];
    const float* embed = (const float*)d_in[1];
    const float* W     = (const float*)d_in[2]; // (L, 512, 1536)
    const float* b     = (const float*)d_in[3]; // (L, 1024)
    const float* Wc    = (const float*)d_in[4]; // (512, 10)
    const float* bc    = (const float*)d_in[5]; // (10,)
    float* out = (float*)d_out;

    float *Ac, *Bc, *ci, *pm, *pool;
    __half *U, *AhA, *AhB, *Bh;
    cudaGetSymbolAddress((void**)&U,   g_U);
    cudaGetSymbolAddress((void**)&AhA, g_AhA);
    cudaGetSymbolAddress((void**)&AhB, g_AhB);
    cudaGetSymbolAddress((void**)&Bh,  g_Bh);
    cudaGetSymbolAddress((void**)&Ac,  g_Ac);
    cudaGetSymbolAddress((void**)&Bc,  g_Bc);
    cudaGetSymbolAddress((void**)&ci,  g_ci);
    cudaGetSymbolAddress((void**)&pm,  g_pm);
    cudaGetSymbolAddress((void**)&pool, g_pool);

    cudaFuncSetAttribute(gemm_mma_kernel, cudaFuncAttributeMaxDynamicSharedMemorySize, DYN_SMEM);

    // weight conversion (both layers at once)
    convert_kernel<<<(2 * K_SZ * N3 / 4) / 256, 256>>>(W, Bh);

    // embedding gather -> fp16 h (buffer A)
    gather_kernel<<<(M_SZ * 128) / 256, 256>>>(x, embed, AhA);

    dim3 gemmGrid(NTILES, MTILES); // x fastest -> 12 CTAs share one A tile via L2
    const int scan8Blocks = (NCHUNK * NCH / 8) / 256;   // 512

    // layer 0: AhA -> AhB
    gemm_mma_kernel<<<gemmGrid, 256, DYN_SMEM>>>(AhA, Bh, b, U);
    scan_passA<<<scan8Blocks, 256>>>(U, Ac, Bc);
    scan_passB<<<(NCH / 4) / 256, 256>>>(Ac, Bc, ci);
    scan_passC<<<scan8Blocks, 256>>>(U, ci, AhA, AhB, pm, 0);

    // layer 1: AhB -> (pooled chunk maxima)
    gemm_mma_kernel<<<gemmGrid, 256, DYN_SMEM>>>(AhB, Bh + (size_t)K_SZ * N3, b + 2 * H_SZ, U);
    scan_passA<<<scan8Blocks, 256>>>(U, Ac, Bc);
    scan_passB<<<(NCH / 4) / 256, 256>>>(Ac, Bc, ci);
    scan_passC<<<scan8Blocks, 256>>>(U, ci, AhB, AhA, pm, 1);

    // pool + classifier
    pool_reduce<<<(NCH / 4) / 256, 256>>>(pm, pool);
    classifier_kernel<<<1, B_SZ * C_SZ>>>(pool, Wc, bc, out);
}

// round 16
// speedup vs baseline: 1.1327x; 1.1327x over previous
#include <cuda_runtime.h>
#include <cuda_fp16.h>
#include <math.h>
#include <stdint.h>

#define S_LEN   2048
#define B_SZ    32
#define D_SZ    512
#define H_SZ    512
#define N3      1536            // 3*H
#define M_SZ    (S_LEN * B_SZ)  // 65536
#define K_SZ    512
#define CHUNK   32
#define NCHUNK  (S_LEN / CHUNK) // 64
#define NCH     (B_SZ * H_SZ)   // 16384
#define C_SZ    10

// ---------------- GEMM tiling ----------------
#define BM 128
#define BN 128
#define BK 32
#define KT_ITERS (K_SZ / BK)    // 16
#define MTILES (M_SZ / BM)      // 512

// smem pitches (bytes), padded for conflict-free ldmatrix
#define A_PITCH 80              // 32 fp16 = 64B + 16B pad
#define B_PITCH 272             // 128 fp16 = 256B + 16B pad
#define ST_A    0
#define ST_B    (BM * A_PITCH)                 // 10240
#define ST_BYTES (BM * A_PITCH + BK * B_PITCH) // 18944
#define XT_STAGES 5
#define GATE_STAGES 4
#define DYN_SMEM_XT   (XT_STAGES * ST_BYTES)   // 94720 -> 2 CTAs/SM
#define DYN_SMEM_GATE (GATE_STAGES * ST_BYTES) // 75776 -> 3 CTAs/SM
#define EPI_PITCH 272                          // staging: 128*272=34816 B, fits both

// ---------------- scratch (device globals: allocation-free rule) ----------------
__device__ __half  g_U  [(size_t)M_SZ * N3];    // 192 MB (fp16 U)
__device__ __half  g_AhA[(size_t)M_SZ * K_SZ];  // 64 MB  (fp16 h, buffer A)
__device__ __half  g_AhB[(size_t)M_SZ * K_SZ];  // 64 MB  (fp16 h, buffer B)
__device__ __half  g_Bh [2 * K_SZ * N3];        // 3 MB   (fp16 W)
__device__ float   g_Ac[NCHUNK * NCH];
__device__ float   g_Bc[NCHUNK * NCH];
__device__ float   g_ci[NCHUNK * NCH];
__device__ float   g_pm[NCHUNK * NCH];          // 4 MB (chunk-level max)
__device__ float   g_pool[NCH];

// ---------------- PTX helpers ----------------
__device__ __forceinline__ uint32_t smem_u32(const void* p) {
    uint32_t a;
    asm("{ .reg .u64 t; cvta.to.shared.u64 t, %1; cvt.u32.u64 %0, t; }" : "=r"(a) : "l"(p));
    return a;
}

__device__ __forceinline__ void cp16(uint32_t dst, const void* src) {
    asm volatile("cp.async.cg.shared.global [%0], [%1], 16;" :: "r"(dst), "l"(src));
}
#define CP_COMMIT() asm volatile("cp.async.commit_group;" ::: "memory")
#define CP_WAIT(n)  asm volatile("cp.async.wait_group %0;" :: "n"(n) : "memory")

__device__ __forceinline__ void ldsm_x4(uint32_t& r0, uint32_t& r1, uint32_t& r2, uint32_t& r3,
                                        uint32_t addr) {
    asm volatile("ldmatrix.sync.aligned.m8n8.x4.shared.b16 {%0,%1,%2,%3}, [%4];"
                 : "=r"(r0), "=r"(r1), "=r"(r2), "=r"(r3) : "r"(addr));
}
__device__ __forceinline__ void ldsm_x4_t(uint32_t& r0, uint32_t& r1, uint32_t& r2, uint32_t& r3,
                                          uint32_t addr) {
    asm volatile("ldmatrix.sync.aligned.m8n8.x4.trans.shared.b16 {%0,%1,%2,%3}, [%4];"
                 : "=r"(r0), "=r"(r1), "=r"(r2), "=r"(r3) : "r"(addr));
}

__device__ __forceinline__ void mma_f16(float& c0, float& c1, float& c2, float& c3,
                                        uint32_t a0, uint32_t a1, uint32_t a2, uint32_t a3,
                                        uint32_t b0, uint32_t b1) {
    asm volatile(
        "mma.sync.aligned.m16n8k16.row.col.f32.f16.f16.f32 "
        "{%0,%1,%2,%3}, {%4,%5,%6,%7}, {%8,%9}, {%0,%1,%2,%3};"
        : "+f"(c0), "+f"(c1), "+f"(c2), "+f"(c3)
        : "r"(a0), "r"(a1), "r"(a2), "r"(a3), "r"(b0), "r"(b1));
}

// fp16 accumulator variant: D/C are 2x .f16x2 regs
__device__ __forceinline__ void mma_f16acc(uint32_t& c0, uint32_t& c1,
                                           uint32_t a0, uint32_t a1, uint32_t a2, uint32_t a3,
                                           uint32_t b0, uint32_t b1) {
    asm volatile(
        "mma.sync.aligned.m16n8k16.row.col.f16.f16.f16.f16 "
        "{%0,%1}, {%2,%3,%4,%5}, {%6,%7}, {%0,%1};"
        : "+r"(c0), "+r"(c1)
        : "r"(a0), "r"(a1), "r"(a2), "r"(a3), "r"(b0), "r"(b1));
}

__device__ __forceinline__ float sigm(float x) { return 1.0f / (1.0f + expf(-x)); }

// ---------------- fp16 pack/unpack helpers ----------------
__device__ __forceinline__ uint2 pack_h4(float4 a) {
    __half2 p0 = __floats2half2_rn(a.x, a.y);
    __half2 p1 = __floats2half2_rn(a.z, a.w);
    uint2 r;
    r.x = *reinterpret_cast<uint32_t*>(&p0);
    r.y = *reinterpret_cast<uint32_t*>(&p1);
    return r;
}
__device__ __forceinline__ void unp8(uint4 v, float* o) {
    float2 a = __half22float2(*reinterpret_cast<__half2*>(&v.x));
    float2 b = __half22float2(*reinterpret_cast<__half2*>(&v.y));
    float2 c = __half22float2(*reinterpret_cast<__half2*>(&v.z));
    float2 d = __half22float2(*reinterpret_cast<__half2*>(&v.w));
    o[0] = a.x; o[1] = a.y; o[2] = b.x; o[3] = b.y;
    o[4] = c.x; o[5] = c.y; o[6] = d.x; o[7] = d.y;
}

// ---------------- embedding gather -> fp16 h ----------------
__global__ void gather_kernel(const int* __restrict__ x,
                              const float* __restrict__ embed,
                              __half* __restrict__ ah) {
    size_t idx = (size_t)blockIdx.x * blockDim.x + threadIdx.x;
    int m = (int)(idx >> 7);
    int j = (int)(idx & 127);
    int row = x[m];
    float4 a = reinterpret_cast<const float4*>(embed)[(size_t)row * 128 + j];
    reinterpret_cast<uint2*>(ah)[idx] = pack_h4(a);
}

// ---------------- weight conversion: fp32 -> fp16 ----------------
__global__ void convert_kernel(const float* __restrict__ src,
                               __half* __restrict__ dst) {
    size_t idx = (size_t)blockIdx.x * blockDim.x + threadIdx.x;
    float4 a = reinterpret_cast<const float4*>(src)[idx];
    reinterpret_cast<uint2*>(dst)[idx] = pack_h4(a);
}

// ================= xt GEMM: ntiles 0..3, fp32 acc, 5-stage, 2 CTAs/SM (R13 proven) =========
__global__ __launch_bounds__(256, 2) void gemm_xt_kernel(
    const __half* __restrict__ Ah,
    const __half* __restrict__ Bh,
    __half* __restrict__ U)
{
    extern __shared__ __align__(1024) char smem[];

    const int tid = threadIdx.x;
    const int lane = tid & 31;
    const int wid = tid >> 5;
    const int wm = wid >> 2;
    const int wn = wid & 3;
    const int n0 = blockIdx.x * BN;        // 0..3 -> xt columns
    const int m0 = blockIdx.y * BM;

    const uint32_t sbase = smem_u32(smem);
    const int lrow = lane & 15;
    const int lcol8 = (lane >> 4) * 8;

    auto load_stage = [&](int kt, int st) {
        uint32_t sb = sbase + st * ST_BYTES;
        int kk = kt * BK;
#pragma unroll
        for (int c = 0; c < 2; c++) {
            int ci = tid + c * 256;
            int am = ci >> 2, ak = ci & 3;
            cp16(sb + ST_A + am * A_PITCH + ak * 16,
                 Ah + (size_t)(m0 + am) * K_SZ + kk + ak * 8);
            int bk = ci >> 4, bq = ci & 15;
            cp16(sb + ST_B + bk * B_PITCH + bq * 16,
                 Bh + (size_t)(kk + bk) * N3 + n0 + bq * 8);
        }
    };

    float acc[4][4][4];
#pragma unroll
    for (int i = 0; i < 4; i++)
#pragma unroll
        for (int j = 0; j < 4; j++)
#pragma unroll
            for (int q = 0; q < 4; q++) acc[i][j][q] = 0.0f;

    load_stage(0, 0); CP_COMMIT();
    load_stage(1, 1); CP_COMMIT();
    load_stage(2, 2); CP_COMMIT();
    load_stage(3, 3); CP_COMMIT();

    for (int kt = 0; kt < KT_ITERS; kt++) {
        const int st = kt % XT_STAGES;
        CP_WAIT(3);
        __syncthreads();

        if (kt + 4 < KT_ITERS) load_stage(kt + 4, (kt + 4) % XT_STAGES);
        CP_COMMIT();

        const uint32_t sb = sbase + st * ST_BYTES;
        const uint32_t sA = sb + ST_A + (wm * 64 + lrow) * A_PITCH;
        const uint32_t sB = sb + ST_B + lrow * B_PITCH + (wn * 32 + lcol8) * 2;

#pragma unroll
        for (int k16 = 0; k16 < 2; k16++) {
            uint32_t bh[2][4];
#pragma unroll
            for (int nj = 0; nj < 2; nj++) {
                uint32_t bo = k16 * 16 * B_PITCH + nj * 16 * 2;
                ldsm_x4_t(bh[nj][0], bh[nj][1], bh[nj][2], bh[nj][3], sB + bo);
            }
#pragma unroll
            for (int mi = 0; mi < 4; mi++) {
                uint32_t ah[4];
                uint32_t ao = mi * 16 * A_PITCH + (k16 * 16 + lcol8) * 2;
                ldsm_x4(ah[0], ah[1], ah[2], ah[3], sA + ao);
#pragma unroll
                for (int n8 = 0; n8 < 4; n8++) {
                    float* c = acc[mi][n8];
                    mma_f16(c[0], c[1], c[2], c[3], ah[0], ah[1], ah[2], ah[3],
                            bh[n8 >> 1][(n8 & 1) * 2], bh[n8 >> 1][(n8 & 1) * 2 + 1]);
                }
            }
        }
    }

    // staged epilogue (no gate)
    __syncthreads();
    const int g = lane >> 2;
    const int tig = lane & 3;
#pragma unroll
    for (int mi = 0; mi < 4; mi++) {
        int row_l = wm * 64 + mi * 16 + g;
#pragma unroll
        for (int n8 = 0; n8 < 4; n8++) {
            int coll = wn * 32 + n8 * 8 + tig * 2;
            *reinterpret_cast<__half2*>(smem + row_l * EPI_PITCH + coll * 2) =
                __floats2half2_rn(acc[mi][n8][0], acc[mi][n8][1]);
            *reinterpret_cast<__half2*>(smem + (row_l + 8) * EPI_PITCH + coll * 2) =
                __floats2half2_rn(acc[mi][n8][2], acc[mi][n8][3]);
        }
    }
    __syncthreads();
#pragma unroll
    for (int j = 0; j < 8; j++) {
        int idx = tid + j * 256;
        int row = idx >> 4, q = idx & 15;
        uint4 v = *reinterpret_cast<uint4*>(smem + row * EPI_PITCH + q * 16);
        *reinterpret_cast<uint4*>(&U[(size_t)(m0 + row) * N3 + n0 + q * 8]) = v;
    }
}

// ================= gate GEMM: ntiles 4..11, fp16 acc, 4-stage, 3 CTAs/SM ===================
__global__ __launch_bounds__(256, 3) void gemm_gate_kernel(
    const __half* __restrict__ Ah,
    const __half* __restrict__ Bh,
    const float* __restrict__ bias,   // 1024 (f then r)
    __half* __restrict__ U)
{
    extern __shared__ __align__(1024) char smem[];
    __shared__ float s_bias[BN];

    const int tid = threadIdx.x;
    const int lane = tid & 31;
    const int wid = tid >> 5;
    const int wm = wid >> 2;
    const int wn = wid & 3;
    const int n0 = 512 + blockIdx.x * BN;  // gate columns
    const int m0 = blockIdx.y * BM;

    if (tid < BN) s_bias[tid] = bias[n0 - 512 + tid];

    const uint32_t sbase = smem_u32(smem);
    const int lrow = lane & 15;
    const int lcol8 = (lane >> 4) * 8;

    auto load_stage = [&](int kt, int st) {
        uint32_t sb = sbase + st * ST_BYTES;
        int kk = kt * BK;
#pragma unroll
        for (int c = 0; c < 2; c++) {
            int ci = tid + c * 256;
            int am = ci >> 2, ak = ci & 3;
            cp16(sb + ST_A + am * A_PITCH + ak * 16,
                 Ah + (size_t)(m0 + am) * K_SZ + kk + ak * 8);
            int bk = ci >> 4, bq = ci & 15;
            cp16(sb + ST_B + bk * B_PITCH + bq * 16,
                 Bh + (size_t)(kk + bk) * N3 + n0 + bq * 8);
        }
    };

    uint32_t acc[4][4][2];   // fp16x2 accumulators: 32 regs
#pragma unroll
    for (int i = 0; i < 4; i++)
#pragma unroll
        for (int j = 0; j < 4; j++) { acc[i][j][0] = 0u; acc[i][j][1] = 0u; }

    load_stage(0, 0); CP_COMMIT();
    load_stage(1, 1); CP_COMMIT();
    load_stage(2, 2); CP_COMMIT();

    for (int kt = 0; kt < KT_ITERS; kt++) {
        const int st = kt % GATE_STAGES;
        CP_WAIT(2);
        __syncthreads();   // stage kt readable; slot (kt+3)%4 = (kt-1)%4 drained

        if (kt + 3 < KT_ITERS) load_stage(kt + 3, (kt + 3) % GATE_STAGES);
        CP_COMMIT();

        const uint32_t sb = sbase + st * ST_BYTES;
        const uint32_t sA = sb + ST_A + (wm * 64 + lrow) * A_PITCH;
        const uint32_t sB = sb + ST_B + lrow * B_PITCH + (wn * 32 + lcol8) * 2;

#pragma unroll
        for (int k16 = 0; k16 < 2; k16++) {
            uint32_t bh[2][4];
#pragma unroll
            for (int nj = 0; nj < 2; nj++) {
                uint32_t bo = k16 * 16 * B_PITCH + nj * 16 * 2;
                ldsm_x4_t(bh[nj][0], bh[nj][1], bh[nj][2], bh[nj][3], sB + bo);
            }
#pragma unroll
            for (int mi = 0; mi < 4; mi++) {
                uint32_t ah[4];
                uint32_t ao = mi * 16 * A_PITCH + (k16 * 16 + lcol8) * 2;
                ldsm_x4(ah[0], ah[1], ah[2], ah[3], sA + ao);
#pragma unroll
                for (int n8 = 0; n8 < 4; n8++) {
                    mma_f16acc(acc[mi][n8][0], acc[mi][n8][1],
                               ah[0], ah[1], ah[2], ah[3],
                               bh[n8 >> 1][(n8 & 1) * 2], bh[n8 >> 1][(n8 & 1) * 2 + 1]);
                }
            }
        }
    }

    // staged epilogue with bias + sigmoid
    __syncthreads();
    const int g = lane >> 2;
    const int tig = lane & 3;
#pragma unroll
    for (int mi = 0; mi < 4; mi++) {
        int row_l = wm * 64 + mi * 16 + g;
#pragma unroll
        for (int n8 = 0; n8 < 4; n8++) {
            int coll = wn * 32 + n8 * 8 + tig * 2;
            float2 p0 = __half22float2(*reinterpret_cast<__half2*>(&acc[mi][n8][0]));
            float2 p1 = __half22float2(*reinterpret_cast<__half2*>(&acc[mi][n8][1]));
            float b0 = s_bias[coll], b1 = s_bias[coll + 1];
            float v0 = sigm(p0.x + b0), v1 = sigm(p0.y + b1);
            float v2 = sigm(p1.x + b0), v3 = sigm(p1.y + b1);
            *reinterpret_cast<__half2*>(smem + row_l * EPI_PITCH + coll * 2) =
                __floats2half2_rn(v0, v1);
            *reinterpret_cast<__half2*>(smem + (row_l + 8) * EPI_PITCH + coll * 2) =
                __floats2half2_rn(v2, v3);
        }
    }
    __syncthreads();
#pragma unroll
    for (int j = 0; j < 8; j++) {
        int idx = tid + j * 256;
        int row = idx >> 4, q = idx & 15;
        uint4 v = *reinterpret_cast<uint4*>(smem + row * EPI_PITCH + q * 16);
        *reinterpret_cast<uint4*>(&U[(size_t)(m0 + row) * N3 + n0 + q * 8]) = v;
    }
}

// ---------------- scan pass A: per-chunk affine composition (8 channels/thread) ----------------
__global__ void scan_passA(const __half* __restrict__ U,
                           float* __restrict__ Ac, float* __restrict__ Bc) {
    int t = blockIdx.x * blockDim.x + threadIdx.x;
    int chv = t & (NCH / 8 - 1);
    int chunk = t >> 11;
    int ch0 = chv * 8;
    int b = ch0 >> 9;
    int h = ch0 & 511;
    const __half* fp = U + ((size_t)(chunk * CHUNK * B_SZ + b)) * N3 + 512 + h;
    float Aa[8], Bb[8];
#pragma unroll
    for (int j = 0; j < 8; j++) { Aa[j] = 1.0f; Bb[j] = 0.0f; }
#pragma unroll 4
    for (int i = 0; i < CHUNK; i++) {
        float f[8], xt[8];
        unp8(*reinterpret_cast<const uint4*>(fp), f);
        unp8(*reinterpret_cast<const uint4*>(fp - 512), xt);
#pragma unroll
        for (int j = 0; j < 8; j++) {
            Bb[j] = f[j] * Bb[j] + (1.0f - f[j]) * xt[j];
            Aa[j] *= f[j];
        }
        fp += (size_t)B_SZ * N3;
    }
    int base = chunk * NCH + ch0;
    *reinterpret_cast<float4*>(&Ac[base])     = make_float4(Aa[0], Aa[1], Aa[2], Aa[3]);
    *reinterpret_cast<float4*>(&Ac[base + 4]) = make_float4(Aa[4], Aa[5], Aa[6], Aa[7]);
    *reinterpret_cast<float4*>(&Bc[base])     = make_float4(Bb[0], Bb[1], Bb[2], Bb[3]);
    *reinterpret_cast<float4*>(&Bc[base + 4]) = make_float4(Bb[4], Bb[5], Bb[6], Bb[7]);
}

// ---------------- scan pass B: prefix over chunks (4 channels/thread) ----------------
__global__ void scan_passB(const float* __restrict__ Ac,
                           const float* __restrict__ Bc,
                           float* __restrict__ ci) {
    int t = blockIdx.x * blockDim.x + threadIdx.x;
    int ch0 = t * 4;
    float4 c = make_float4(0.f, 0.f, 0.f, 0.f);
#pragma unroll 8
    for (int k = 0; k < NCHUNK; k++) {
        int base = k * NCH + ch0;
        *reinterpret_cast<float4*>(&ci[base]) = c;
        float4 A = *reinterpret_cast<const float4*>(&Ac[base]);
        float4 B = *reinterpret_cast<const float4*>(&Bc[base]);
        c.x = A.x * c.x + B.x;
        c.y = A.y * c.y + B.y;
        c.z = A.z * c.z + B.z;
        c.w = A.w * c.w + B.w;
    }
}

// ---------------- scan pass C: rescan + highway output (8 channels/thread) ----------------
__global__ void scan_passC(const __half* __restrict__ U,
                           const float* __restrict__ ci,
                           const __half* __restrict__ hin,
                           __half* __restrict__ hout,
                           float* __restrict__ pm,
                           int mode) {
    int t = blockIdx.x * blockDim.x + threadIdx.x;
    int chv = t & (NCH / 8 - 1);
    int chunk = t >> 11;
    int ch0 = chv * 8;
    int b = ch0 >> 9;
    int h = ch0 & 511;
    size_t m0 = (size_t)(chunk * CHUNK * B_SZ + b);
    const __half* fp = U + m0 * N3 + 512 + h;
    size_t hoff = m0 * H_SZ + h;
    int cbase = chunk * NCH + ch0;

    float c[8], mx[8];
    *reinterpret_cast<float4*>(&c[0]) = *reinterpret_cast<const float4*>(&ci[cbase]);
    *reinterpret_cast<float4*>(&c[4]) = *reinterpret_cast<const float4*>(&ci[cbase + 4]);
#pragma unroll
    for (int j = 0; j < 8; j++) mx[j] = -INFINITY;

#pragma unroll 2
    for (int i = 0; i < CHUNK; i++) {
        float f[8], xt[8], r[8], hv[8];
        unp8(*reinterpret_cast<const uint4*>(fp), f);
        unp8(*reinterpret_cast<const uint4*>(fp - 512), xt);
        unp8(*reinterpret_cast<const uint4*>(fp + 512), r);
        unp8(*reinterpret_cast<const uint4*>(&hin[hoff]), hv);
        if (mode == 0) {
            __half ob[8];
#pragma unroll
            for (int j = 0; j < 8; j++) {
                c[j] = f[j] * c[j] + (1.0f - f[j]) * xt[j];
                float o = r[j] * tanhf(c[j]) + (1.0f - r[j]) * hv[j];
                ob[j] = __float2half_rn(o);
            }
            *reinterpret_cast<uint4*>(&hout[hoff]) = *reinterpret_cast<uint4*>(ob);
        } else {
#pragma unroll
            for (int j = 0; j < 8; j++) {
                c[j] = f[j] * c[j] + (1.0f - f[j]) * xt[j];
                float o = r[j] * tanhf(c[j]) + (1.0f - r[j]) * hv[j];
                mx[j] = fmaxf(mx[j], o);
            }
        }
        fp += (size_t)B_SZ * N3;
        hoff += (size_t)B_SZ * H_SZ;
    }
    if (mode == 1) {
        *reinterpret_cast<float4*>(&pm[cbase])     = make_float4(mx[0], mx[1], mx[2], mx[3]);
        *reinterpret_cast<float4*>(&pm[cbase + 4]) = make_float4(mx[4], mx[5], mx[6], mx[7]);
    }
}

// ---------------- pool reduce over chunks (4 channels/thread) ----------------
__global__ void pool_reduce(const float* __restrict__ pm, float* __restrict__ pool) {
    int t = blockIdx.x * blockDim.x + threadIdx.x;
    int ch0 = t * 4;
    float4 mx = make_float4(-INFINITY, -INFINITY, -INFINITY, -INFINITY);
#pragma unroll 8
    for (int s = 0; s < NCHUNK; s++) {
        float4 v = *reinterpret_cast<const float4*>(&pm[s * NCH + ch0]);
        mx.x = fmaxf(mx.x, v.x); mx.y = fmaxf(mx.y, v.y);
        mx.z = fmaxf(mx.z, v.z); mx.w = fmaxf(mx.w, v.w);
    }
    pool[ch0]     = tanhf(tanhf(mx.x));
    pool[ch0 + 1] = tanhf(tanhf(mx.y));
    pool[ch0 + 2] = tanhf(tanhf(mx.z));
    pool[ch0 + 3] = tanhf(tanhf(mx.w));
}

// ---------------- tiny classifier ----------------
__global__ void classifier_kernel(const float* __restrict__ pool,
                                  const float* __restrict__ Wc,
                                  const float* __restrict__ bc,
                                  float* __restrict__ out) {
    int tid = threadIdx.x;
    int b = tid / C_SZ;
    int c = tid % C_SZ;
    float s = bc[c];
    const float* p = pool + b * H_SZ;
#pragma unroll 8
    for (int h = 0; h < H_SZ; h++) s += p[h] * Wc[h * C_SZ + c];
    out[b * C_SZ + c] = s;
}

// ---------------- launch ----------------
extern "C" void kernel_launch(void* const* d_in, const int* in_sizes, int n_in,
                              void* d_out, int out_size) {
    const int*   x     = (const int*)d_in[0];
    const float* embed = (const float*)d_in[1];
    const float* W     = (const float*)d_in[2]; // (L, 512, 1536)
    const float* b     = (const float*)d_in[3]; // (L, 1024)
    const float* Wc    = (const float*)d_in[4]; // (512, 10)
    const float* bc    = (const float*)d_in[5]; // (10,)
    float* out = (float*)d_out;

    float *Ac, *Bc, *ci, *pm, *pool;
    __half *U, *AhA, *AhB, *Bh;
    cudaGetSymbolAddress((void**)&U,   g_U);
    cudaGetSymbolAddress((void**)&AhA, g_AhA);
    cudaGetSymbolAddress((void**)&AhB, g_AhB);
    cudaGetSymbolAddress((void**)&Bh,  g_Bh);
    cudaGetSymbolAddress((void**)&Ac,  g_Ac);
    cudaGetSymbolAddress((void**)&Bc,  g_Bc);
    cudaGetSymbolAddress((void**)&ci,  g_ci);
    cudaGetSymbolAddress((void**)&pm,  g_pm);
    cudaGetSymbolAddress((void**)&pool, g_pool);

    cudaFuncSetAttribute(gemm_xt_kernel, cudaFuncAttributeMaxDynamicSharedMemorySize, DYN_SMEM_XT);
    cudaFuncSetAttribute(gemm_gate_kernel, cudaFuncAttributeMaxDynamicSharedMemorySize, DYN_SMEM_GATE);

    // weight conversion (both layers at once)
    convert_kernel<<<(2 * K_SZ * N3 / 4) / 256, 256>>>(W, Bh);

    // embedding gather -> fp16 h (buffer A)
    gather_kernel<<<(M_SZ * 128) / 256, 256>>>(x, embed, AhA);

    dim3 xtGrid(4, MTILES);     // xt columns
    dim3 gateGrid(8, MTILES);   // gate columns
    const int scan8Blocks = (NCHUNK * NCH / 8) / 256;

    const __half* Bh1 = Bh + (size_t)K_SZ * N3;

    // layer 0: AhA -> AhB
    gemm_gate_kernel<<<gateGrid, 256, DYN_SMEM_GATE>>>(AhA, Bh, b, U);
    gemm_xt_kernel<<<xtGrid, 256, DYN_SMEM_XT>>>(AhA, Bh, U);
    scan_passA<<<scan8Blocks, 256>>>(U, Ac, Bc);
    scan_passB<<<(NCH / 4) / 256, 256>>>(Ac, Bc, ci);
    scan_passC<<<scan8Blocks, 256>>>(U, ci, AhA, AhB, pm, 0);

    // layer 1: AhB -> (pooled chunk maxima)
    gemm_gate_kernel<<<gateGrid, 256, DYN_SMEM_GATE>>>(AhB, Bh1, b + 2 * H_SZ, U);
    gemm_xt_kernel<<<xtGrid, 256, DYN_SMEM_XT>>>(AhB, Bh1, U);
    scan_passA<<<scan8Blocks, 256>>>(U, Ac, Bc);
    scan_passB<<<(NCH / 4) / 256, 256>>>(Ac, Bc, ci);
    scan_passC<<<scan8Blocks, 256>>>(U, ci, AhB, AhA, pm, 1);

    // pool + classifier
    pool_reduce<<<(NCH / 4) / 256, 256>>>(pm, pool);
    classifier_kernel<<<1, B_SZ * C_SZ>>>(pool, Wc, bc, out);
}